// round 14
// baseline (speedup 1.0000x reference)
#include <cuda_runtime.h>
#include <cuda_bf16.h>
#include <math.h>
#include <stdint.h>

// ---------------- problem constants ----------------
#define BB   32
#define HH   56
#define WW   56
#define CC   256
#define WS   7
#define NH   8
#define HD   32
#define KCH  16
#define KSPT 28
#define NT   49          // tokens per window
#define MLPH 1024
#define LL   (HH*WW)     // 3136
#define ROWS (BB*LL)     // 100352
#define BW   2048        // windows
#define BN   (BW*NH)     // 16384
#define MV   (BW*KSPT)   // 57344 (v rows)
#define SCALE_F 0.17677669529663687f   // 32^-0.5

// ---------------- static scratch (no allocations allowed) ----------------
__device__ __nv_bfloat16 g_xw_bf[ROWS*CC];        // LN1 windowed (bf16) -> q gemm A
__device__ __nv_bfloat16 g_q_bf[ROWS*CC];         // q bf16 (topk reads)
__device__ __nv_bfloat16 g_qcha1_bf[BW*NT*(CC/2)];// channel-gathered q (bf16)
__device__ __nv_bfloat16 g_k_bf[ROWS*(CC/2)];     // k bf16 (attn reads)
__device__ __nv_bfloat16 g_vbuf_bf[MV*CC];        // gathered v input (bf16)
__device__ __nv_bfloat16 g_vproj_bf[MV*CC];       // v projected bf16 (attn reads)
__device__ __nv_bfloat16 g_obuf_bf[ROWS*CC];      // attn out (bf16) -> proj gemm A
__device__ __nv_bfloat16 g_xn2_bf[ROWS*CC];       // LN2 out (bf16) -> mlp1 A
__device__ __nv_bfloat16 g_h_bf[(size_t)ROWS*MLPH]; // mlp hidden (bf16)
__device__ int           g_sidx[BN*KSPT];
// transposed bf16 weights (N-major, K contiguous)
__device__ __nv_bfloat16 g_wq_t[CC*CC];
__device__ __nv_bfloat16 g_wk_t[(CC/2)*(CC/2)];
__device__ __nv_bfloat16 g_wv_t[CC*CC];
__device__ __nv_bfloat16 g_wproj_t[CC*CC];
__device__ __nv_bfloat16 g_w1_t[CC*MLPH];
__device__ __nv_bfloat16 g_w2_t[MLPH*CC];

// ---------------- small helpers ----------------
__device__ __forceinline__ float gelu_exact(float x) {
    return 0.5f * x * (1.0f + erff(x * 0.70710678118654752f));
}

__device__ __forceinline__ uint32_t smem_u32(const void* p) {
    return (uint32_t)__cvta_generic_to_shared(p);
}
__device__ __forceinline__ void cp_async16(uint32_t smem_dst, const void* gmem_src) {
    asm volatile("cp.async.ca.shared.global [%0], [%1], 16;\n" :: "r"(smem_dst), "l"(gmem_src));
}
#define CP_COMMIT()  asm volatile("cp.async.commit_group;\n" ::: "memory")
#define CP_WAIT(n)   asm volatile("cp.async.wait_group %0;\n" :: "n"(n) : "memory")

__device__ __forceinline__ void mma_bf16(float c[4], const uint32_t a[4], const uint32_t b[2]) {
    asm volatile(
        "mma.sync.aligned.m16n8k16.row.col.f32.bf16.bf16.f32 "
        "{%0,%1,%2,%3},{%4,%5,%6,%7},{%8,%9},{%0,%1,%2,%3};"
        : "+f"(c[0]), "+f"(c[1]), "+f"(c[2]), "+f"(c[3])
        : "r"(a[0]), "r"(a[1]), "r"(a[2]), "r"(a[3]), "r"(b[0]), "r"(b[1]));
}

__device__ __forceinline__ void ldsm_x4(uint32_t r[4], uint32_t addr) {
    asm volatile("ldmatrix.sync.aligned.m8n8.x4.shared.b16 {%0,%1,%2,%3}, [%4];"
        : "=r"(r[0]), "=r"(r[1]), "=r"(r[2]), "=r"(r[3]) : "r"(addr));
}
__device__ __forceinline__ void ldsm_x2(uint32_t r[2], uint32_t addr) {
    asm volatile("ldmatrix.sync.aligned.m8n8.x2.shared.b16 {%0,%1}, [%2];"
        : "=r"(r[0]), "=r"(r[1]) : "r"(addr));
}

// window-layout row -> (B, H*W) row
__device__ __forceinline__ int winrev_row(int wr) {
    int widx = wr / NT, token = wr % NT;
    int b = widx >> 6, rem = widx & 63;
    int wh = rem >> 3, ww = rem & 7;
    int h = wh * WS + token / WS;
    int w = ww * WS + token % WS;
    return b * LL + h * WW + w;
}

// ---------------- fused weight transpose+convert (all 6 weights, 1 launch) ----------------
__global__ void wtrans_all_kernel(
    const float* __restrict__ wq, __nv_bfloat16* __restrict__ wqt,
    const float* __restrict__ wk, __nv_bfloat16* __restrict__ wkt,
    const float* __restrict__ wv, __nv_bfloat16* __restrict__ wvt,
    const float* __restrict__ wp, __nv_bfloat16* __restrict__ wpt,
    const float* __restrict__ w1, __nv_bfloat16* __restrict__ w1t,
    const float* __restrict__ w2, __nv_bfloat16* __restrict__ w2t) {
    __shared__ float t[32][33];
    int bid = blockIdx.x;
    const float* W; __nv_bfloat16* Wt; int K, N, local;
    if      (bid < 64)  { W = wq; Wt = wqt; K = 256;  N = 256;  local = bid; }
    else if (bid < 80)  { W = wk; Wt = wkt; K = 128;  N = 128;  local = bid - 64; }
    else if (bid < 144) { W = wv; Wt = wvt; K = 256;  N = 256;  local = bid - 80; }
    else if (bid < 208) { W = wp; Wt = wpt; K = 256;  N = 256;  local = bid - 144; }
    else if (bid < 464) { W = w1; Wt = w1t; K = 256;  N = 1024; local = bid - 208; }
    else                { W = w2; Wt = w2t; K = 1024; N = 256;  local = bid - 464; }
    int tpx = N >> 5;
    int txi = local % tpx, tyi = local / tpx;
    int k0 = tyi * 32, n0 = txi * 32;
    int tx = threadIdx.x, ty = threadIdx.y;   // 32 x 8
    for (int i = ty; i < 32; i += 8) t[i][tx] = W[(size_t)(k0 + i) * N + n0 + tx];
    __syncthreads();
    for (int i = ty; i < 32; i += 8)
        Wt[(size_t)(n0 + i) * K + k0 + tx] = __float2bfloat16(t[tx][i]);
}

// ---------------- bf16 HMMA GEMM, 3-stage cp.async pipeline ----------------
#define TSTR 72
#define TBUF (128*TSTR)
#define GEMM_SMEM (6*TBUF*2)   // 3 stages x (A+B) = 110592 bytes

template<int ACT, int OUTF32, int OUTBF, int WREV>
__global__ void __launch_bounds__(256, 2)
gemm_bf16_kernel(const __nv_bfloat16* __restrict__ A, const __nv_bfloat16* __restrict__ Bt,
                 const float* __restrict__ bias, const float* __restrict__ res,
                 float* __restrict__ D, __nv_bfloat16* __restrict__ Dbf,
                 int M, int Kt, int Ncols) {
    extern __shared__ __nv_bfloat16 sm[];
    // stage s: A at sm + s*2*TBUF, B at sm + s*2*TBUF + TBUF
    int tid = threadIdx.x;
    int warp = tid >> 5, lane = tid & 31;
    int g = lane >> 2, tig = lane & 3;
    int wm = warp >> 2, wn = warp & 3;   // 2 x 4 warp grid
    int bm = blockIdx.y * 128, bn = blockIdx.x * 128;

    uint32_t a_off = ((uint32_t)(wm*64 + (lane & 15)) * TSTR + (lane >> 4) * 8) * 2;
    uint32_t b_off = ((uint32_t)(wn*32 + (lane & 7)) * TSTR + ((lane >> 3) & 1) * 8) * 2;

    float acc[4][4][4];
    #pragma unroll
    for (int mi = 0; mi < 4; mi++)
        #pragma unroll
        for (int ni = 0; ni < 4; ni++)
            #pragma unroll
            for (int j = 0; j < 4; j++) acc[mi][ni][j] = 0.0f;

    int T = Kt >> 6;

    auto issue = [&](int t, int s) {
        int k0 = t << 6;
        __nv_bfloat16* as = sm + s * 2 * TBUF;
        __nv_bfloat16* bs = as + TBUF;
        #pragma unroll
        for (int i = 0; i < 4; i++) {
            int idx = tid + i * 256;
            int r = idx >> 3, q = idx & 7;
            cp_async16(smem_u32(&as[r * TSTR + q * 8]),
                       A + (size_t)(bm + r) * Kt + k0 + q * 8);
        }
        #pragma unroll
        for (int i = 0; i < 4; i++) {
            int idx = tid + i * 256;
            int r = idx >> 3, q = idx & 7;
            cp_async16(smem_u32(&bs[r * TSTR + q * 8]),
                       Bt + (size_t)(bn + r) * Kt + k0 + q * 8);
        }
        CP_COMMIT();
    };

    issue(0, 0);
    if (T > 1) issue(1, 1);

    for (int t = 0; t < T; t++) {
        if (t + 1 < T) { CP_WAIT(1); } else { CP_WAIT(0); }
        __syncthreads();   // also guarantees stage (t+2)%3 is no longer being read
        if (t + 2 < T) issue(t + 2, (t + 2) % 3);

        int s = t % 3;
        uint32_t as_base = smem_u32(sm + s * 2 * TBUF) + a_off;
        uint32_t bs_base = smem_u32(sm + s * 2 * TBUF + TBUF) + b_off;

        #pragma unroll
        for (int kk = 0; kk < 64; kk += 16) {
            uint32_t af[4][4], bfr[4][2];
            #pragma unroll
            for (int mi = 0; mi < 4; mi++)
                ldsm_x4(af[mi], as_base + (uint32_t)(mi*16*TSTR + kk) * 2);
            #pragma unroll
            for (int ni = 0; ni < 4; ni++)
                ldsm_x2(bfr[ni], bs_base + (uint32_t)(ni*8*TSTR + kk) * 2);
            #pragma unroll
            for (int mi = 0; mi < 4; mi++)
                #pragma unroll
                for (int ni = 0; ni < 4; ni++)
                    mma_bf16(acc[mi][ni], af[mi], bfr[ni]);
        }
    }

    #pragma unroll
    for (int mi = 0; mi < 4; mi++) {
        int r0 = bm + wm*64 + mi*16 + g;
        int r1 = r0 + 8;
        int o0 = WREV ? winrev_row(r0) : r0;
        int o1 = WREV ? winrev_row(r1) : r1;
        #pragma unroll
        for (int ni = 0; ni < 4; ni++) {
            int col = bn + wn*32 + ni*8 + tig*2;
            const float2 bi = *reinterpret_cast<const float2*>(bias + col);
            float v0 = acc[mi][ni][0] + bi.x;
            float v1 = acc[mi][ni][1] + bi.y;
            float v2 = acc[mi][ni][2] + bi.x;
            float v3 = acc[mi][ni][3] + bi.y;
            if (ACT == 1) { v0 = gelu_exact(v0); v1 = gelu_exact(v1); v2 = gelu_exact(v2); v3 = gelu_exact(v3); }
            size_t i0 = (size_t)o0 * Ncols + col;
            size_t i1 = (size_t)o1 * Ncols + col;
            if (res) {
                const float2 ra = *reinterpret_cast<const float2*>(res + i0);
                const float2 rb = *reinterpret_cast<const float2*>(res + i1);
                v0 += ra.x; v1 += ra.y; v2 += rb.x; v3 += rb.y;
            }
            if (OUTF32) {
                *reinterpret_cast<float2*>(D + i0) = make_float2(v0, v1);
                *reinterpret_cast<float2*>(D + i1) = make_float2(v2, v3);
            }
            if (OUTBF) {
                __nv_bfloat162 p0 = __floats2bfloat162_rn(v0, v1);
                __nv_bfloat162 p1 = __floats2bfloat162_rn(v2, v3);
                *reinterpret_cast<__nv_bfloat162*>(Dbf + i0) = p0;
                *reinterpret_cast<__nv_bfloat162*>(Dbf + i1) = p1;
            }
        }
    }
}

// ---------------- warp-per-row LN1 + window partition (bf16 out) ----------------
__global__ void __launch_bounds__(256)
ln1_warp_kernel(const float* __restrict__ x,
                const float* __restrict__ gam, const float* __restrict__ bet) {
    int wid = threadIdx.x >> 5, lane = threadIdx.x & 31;
    int row = blockIdx.x * 8 + wid;
    const float* xr = x + (size_t)row * CC;
    float4 a = *reinterpret_cast<const float4*>(xr + lane*4);
    float4 b = *reinterpret_cast<const float4*>(xr + 128 + lane*4);
    float s = a.x+a.y+a.z+a.w + b.x+b.y+b.z+b.w;
    float s2 = a.x*a.x+a.y*a.y+a.z*a.z+a.w*a.w + b.x*b.x+b.y*b.y+b.z*b.z+b.w*b.w;
    #pragma unroll
    for (int o = 16; o > 0; o >>= 1) {
        s  += __shfl_xor_sync(0xffffffffu, s,  o);
        s2 += __shfl_xor_sync(0xffffffffu, s2, o);
    }
    float mu = s * (1.0f/CC);
    float rstd = rsqrtf(s2 * (1.0f/CC) - mu*mu + 1e-5f);
    int bidx = row / LL, l = row % LL;
    int h = l / WW, w = l % WW;
    int widx = (bidx*8 + h/WS)*8 + (w/WS);
    int token = (h%WS)*WS + (w%WS);
    __nv_bfloat16* dst = g_xw_bf + ((size_t)widx*NT + token)*CC;
    float4 g0 = *reinterpret_cast<const float4*>(gam + lane*4);
    float4 g1 = *reinterpret_cast<const float4*>(gam + 128 + lane*4);
    float4 b0 = *reinterpret_cast<const float4*>(bet + lane*4);
    float4 b1 = *reinterpret_cast<const float4*>(bet + 128 + lane*4);
    __nv_bfloat162 p0 = __floats2bfloat162_rn((a.x-mu)*rstd*g0.x+b0.x, (a.y-mu)*rstd*g0.y+b0.y);
    __nv_bfloat162 p1 = __floats2bfloat162_rn((a.z-mu)*rstd*g0.z+b0.z, (a.w-mu)*rstd*g0.w+b0.w);
    __nv_bfloat162 p2 = __floats2bfloat162_rn((b.x-mu)*rstd*g1.x+b1.x, (b.y-mu)*rstd*g1.y+b1.y);
    __nv_bfloat162 p3 = __floats2bfloat162_rn((b.z-mu)*rstd*g1.z+b1.z, (b.w-mu)*rstd*g1.w+b1.w);
    uint2 u0; u0.x = *reinterpret_cast<uint32_t*>(&p0); u0.y = *reinterpret_cast<uint32_t*>(&p1);
    uint2 u1; u1.x = *reinterpret_cast<uint32_t*>(&p2); u1.y = *reinterpret_cast<uint32_t*>(&p3);
    *reinterpret_cast<uint2*>(dst + lane*4) = u0;
    *reinterpret_cast<uint2*>(dst + 128 + lane*4) = u1;
}

// ---------------- warp-per-row LN2 (bf16 out, linear) ----------------
__global__ void __launch_bounds__(256)
ln2_warp_kernel(const float* __restrict__ x,
                const float* __restrict__ gam, const float* __restrict__ bet) {
    int wid = threadIdx.x >> 5, lane = threadIdx.x & 31;
    int row = blockIdx.x * 8 + wid;
    const float* xr = x + (size_t)row * CC;
    float4 a = *reinterpret_cast<const float4*>(xr + lane*4);
    float4 b = *reinterpret_cast<const float4*>(xr + 128 + lane*4);
    float s = a.x+a.y+a.z+a.w + b.x+b.y+b.z+b.w;
    float s2 = a.x*a.x+a.y*a.y+a.z*a.z+a.w*a.w + b.x*b.x+b.y*b.y+b.z*b.z+b.w*b.w;
    #pragma unroll
    for (int o = 16; o > 0; o >>= 1) {
        s  += __shfl_xor_sync(0xffffffffu, s,  o);
        s2 += __shfl_xor_sync(0xffffffffu, s2, o);
    }
    float mu = s * (1.0f/CC);
    float rstd = rsqrtf(s2 * (1.0f/CC) - mu*mu + 1e-5f);
    __nv_bfloat16* dst = g_xn2_bf + (size_t)row * CC;
    float4 g0 = *reinterpret_cast<const float4*>(gam + lane*4);
    float4 g1 = *reinterpret_cast<const float4*>(gam + 128 + lane*4);
    float4 b0 = *reinterpret_cast<const float4*>(bet + lane*4);
    float4 b1 = *reinterpret_cast<const float4*>(bet + 128 + lane*4);
    __nv_bfloat162 p0 = __floats2bfloat162_rn((a.x-mu)*rstd*g0.x+b0.x, (a.y-mu)*rstd*g0.y+b0.y);
    __nv_bfloat162 p1 = __floats2bfloat162_rn((a.z-mu)*rstd*g0.z+b0.z, (a.w-mu)*rstd*g0.w+b0.w);
    __nv_bfloat162 p2 = __floats2bfloat162_rn((b.x-mu)*rstd*g1.x+b1.x, (b.y-mu)*rstd*g1.y+b1.y);
    __nv_bfloat162 p3 = __floats2bfloat162_rn((b.z-mu)*rstd*g1.z+b1.z, (b.w-mu)*rstd*g1.w+b1.w);
    uint2 u0; u0.x = *reinterpret_cast<uint32_t*>(&p0); u0.y = *reinterpret_cast<uint32_t*>(&p1);
    uint2 u1; u1.x = *reinterpret_cast<uint32_t*>(&p2); u1.y = *reinterpret_cast<uint32_t*>(&p3);
    *reinterpret_cast<uint2*>(dst + lane*4) = u0;
    *reinterpret_cast<uint2*>(dst + 128 + lane*4) = u1;
}

// ---------------- warp-per-(window,head) top-k + gathers (bf16 q) ----------------
#define TKQT  (NT*33)
#define TKREG (TKQT + 49 + 28 + 2)
#define TOPK_SMEM (8*TKREG*4)

__global__ void __launch_bounds__(256)
topk_warp_kernel(const float* __restrict__ wch, const float* __restrict__ bch) {
    extern __shared__ float tsm[];
    int wid = threadIdx.x >> 5, lane = threadIdx.x & 31;
    float* qt  = tsm + wid * TKREG;
    float* tm  = qt + TKQT;
    int*   sidx = (int*)(tm + 49);
    int bn = blockIdx.x * 8 + wid;
    int widx = bn >> 3, nh = bn & 7;

    const __nv_bfloat16* base = g_q_bf + (size_t)widx*NT*CC + nh*HD + lane;
    float cs = 0.0f, cm = -1e30f;
    #pragma unroll
    for (int t = 0; t < NT; t++) {
        float v = __bfloat162float(base[(size_t)t*CC]);
        qt[t*33 + lane] = v;
        cs += v; cm = fmaxf(cm, v);
    }
    float cmean = cs * (1.0f/NT);
    __syncwarp();

    for (int t = lane; t < NT; t += 32) {
        float s = 0.0f;
        #pragma unroll
        for (int hd = 0; hd < HD; hd++) s += qt[t*33 + hd];
        tm[t] = s * (1.0f/HD);
    }
    __syncwarp();

    float sc = bch[lane];
    #pragma unroll
    for (int i = 0; i < HD; i++) {
        float cmi = __shfl_sync(0xffffffffu, cmean, i);
        float cxi = __shfl_sync(0xffffffffu, cm, i);
        sc += cmi * wch[i*HD + lane] + cxi * wch[(HD+i)*HD + lane];
    }
    sc = gelu_exact(sc);

    int cnt = 0;
    #pragma unroll
    for (int j = 0; j < HD; j++) {
        float sj = __shfl_sync(0xffffffffu, sc, j);
        cnt += (sj > sc) || (sj == sc && j < lane);
    }
    int cflag = cnt < KCH;
    unsigned cmask = __ballot_sync(0xffffffffu, cflag);
    int cpos = __popc(cmask & ((1u << lane) - 1u));

    float t0v = tm[lane];
    float t1v = (lane + 32 < NT) ? tm[lane + 32] : -1e30f;
    int scnt0 = 0, scnt1 = 0;
    #pragma unroll
    for (int j = 0; j < NT; j++) {
        float tj = tm[j];
        scnt0 += (tj > t0v) || (tj == t0v && j < lane);
        scnt1 += (tj > t1v) || (tj == t1v && j < lane + 32);
    }
    int sflag0 = scnt0 < KSPT;
    int sflag1 = (lane + 32 < NT) && (scnt1 < KSPT);
    unsigned m0 = __ballot_sync(0xffffffffu, sflag0);
    unsigned m1 = __ballot_sync(0xffffffffu, sflag1);
    if (sflag0) sidx[__popc(m0 & ((1u << lane) - 1u))] = lane;
    if (sflag1) sidx[__popc(m0) + __popc(m1 & ((1u << lane) - 1u))] = lane + 32;
    __syncwarp();

    if (cflag) {
        __nv_bfloat16* dst = g_qcha1_bf + (size_t)widx*NT*(CC/2) + nh*KCH + cpos;
        #pragma unroll
        for (int t = 0; t < NT; t++)
            dst[(size_t)t*(CC/2)] = __float2bfloat16(qt[t*33 + lane]);
    }
    {
        __nv_bfloat16* dst = g_vbuf_bf + (size_t)widx*KSPT*CC + nh*HD + lane;
        #pragma unroll
        for (int s = 0; s < KSPT; s++) {
            int t = sidx[s];
            dst[(size_t)s*CC] = __float2bfloat16(qt[t*33 + lane]);
        }
    }
    if (lane < KSPT) g_sidx[bn*KSPT + lane] = sidx[lane];
}

// ---------------- warp-per-(window,head) attention ----------------
__global__ void __launch_bounds__(256)
attn_warp_kernel(const float* __restrict__ rpb) {
    __shared__ float khs[8][NT*KCH];
    int wid = threadIdx.x >> 5, lane = threadIdx.x & 31;
    int bn = blockIdx.x * 8 + wid;
    int widx = bn >> 3, nh = bn & 7;
    float* kh = khs[wid];

    for (int t = lane; t < NT; t += 32) {
        const __nv_bfloat16* src = g_k_bf + ((size_t)widx*NT + t)*(CC/2) + nh*KCH;
        uint4 a = *reinterpret_cast<const uint4*>(src);
        uint4 b = *reinterpret_cast<const uint4*>(src + 8);
        const __nv_bfloat16* pa = reinterpret_cast<const __nv_bfloat16*>(&a);
        const __nv_bfloat16* pb = reinterpret_cast<const __nv_bfloat16*>(&b);
        #pragma unroll
        for (int j = 0; j < 8; j++) kh[t*KCH + j]     = __bfloat162float(pa[j]);
        #pragma unroll
        for (int j = 0; j < 8; j++) kh[t*KCH + 8 + j] = __bfloat162float(pb[j]);
    }

    float vreg[KSPT];
    #pragma unroll
    for (int s = 0; s < KSPT; s++)
        vreg[s] = __bfloat162float(g_vproj_bf[((size_t)widx*KSPT + s)*CC + nh*HD + lane]);

    float qa[KCH];
    int r2 = 0, c2 = 0;
    if (lane < KSPT) {
        int t2 = g_sidx[bn*KSPT + lane];
        r2 = t2 / WS; c2 = t2 % WS;
        const __nv_bfloat16* src = g_qcha1_bf + ((size_t)widx*NT + t2)*(CC/2) + nh*KCH;
        uint4 a = *reinterpret_cast<const uint4*>(src);
        uint4 b = *reinterpret_cast<const uint4*>(src + 8);
        const __nv_bfloat16* pa = reinterpret_cast<const __nv_bfloat16*>(&a);
        const __nv_bfloat16* pb = reinterpret_cast<const __nv_bfloat16*>(&b);
        #pragma unroll
        for (int j = 0; j < 8; j++) qa[j]     = __bfloat162float(pa[j]) * SCALE_F;
        #pragma unroll
        for (int j = 0; j < 8; j++) qa[8 + j] = __bfloat162float(pb[j]) * SCALE_F;
    } else {
        #pragma unroll
        for (int j = 0; j < KCH; j++) qa[j] = 0.0f;
    }
    __syncwarp();

    __nv_bfloat16* obase = g_obuf_bf + (size_t)widx*NT*CC + nh*HD + lane;
    const float inv_kspt = 1.0f / KSPT;
    for (int t = 0; t < NT; t++) {
        float sum = 0.0f;
        #pragma unroll
        for (int j = 0; j < KCH; j++) sum += kh[t*KCH + j] * qa[j];
        int rt = t / WS, ct = t % WS;
        int rel = (rt - r2 + WS - 1) * (2*WS - 1) + (ct - c2 + WS - 1);
        float at = sum + rpb[rel*NH + nh];
        if (lane >= KSPT) at = -1e30f;
        float m = at;
        #pragma unroll
        for (int o = 16; o > 0; o >>= 1) m = fmaxf(m, __shfl_xor_sync(0xffffffffu, m, o));
        float araw = (lane < KSPT) ? at : 0.0f;
        #pragma unroll
        for (int o = 16; o > 0; o >>= 1) araw += __shfl_xor_sync(0xffffffffu, araw, o);
        float gate = 1.0f / (1.0f + expf(-araw * inv_kspt));
        float e = expf(at - m);
        float es = e;
        #pragma unroll
        for (int o = 16; o > 0; o >>= 1) es += __shfl_xor_sync(0xffffffffu, es, o);
        float p = e * (gate / es);
        float acc = 0.0f;
        #pragma unroll
        for (int s = 0; s < KSPT; s++)
            acc += __shfl_sync(0xffffffffu, p, s) * vreg[s];
        obase[(size_t)t*CC] = __float2bfloat16(acc);
    }
}

// ---------------- launch ----------------
extern "C" void kernel_launch(void* const* d_in, const int* in_sizes, int n_in,
                              void* d_out, int out_size) {
    const float* x       = (const float*)d_in[0];
    const float* norm1_g = (const float*)d_in[1];
    const float* norm1_b = (const float*)d_in[2];
    const float* wq      = (const float*)d_in[3];
    const float* bq      = (const float*)d_in[4];
    const float* wk      = (const float*)d_in[5];
    const float* bk      = (const float*)d_in[6];
    const float* wv      = (const float*)d_in[7];
    const float* bv      = (const float*)d_in[8];
    const float* wproj   = (const float*)d_in[9];
    const float* bproj   = (const float*)d_in[10];
    const float* wch     = (const float*)d_in[11];
    const float* bch     = (const float*)d_in[12];
    const float* rpb     = (const float*)d_in[13];
    const float* norm2_g = (const float*)d_in[14];
    const float* norm2_b = (const float*)d_in[15];
    const float* w1      = (const float*)d_in[16];
    const float* b1      = (const float*)d_in[17];
    const float* w2      = (const float*)d_in[18];
    const float* b2      = (const float*)d_in[19];
    float* out = (float*)d_out;

    __nv_bfloat16 *p_xw_bf, *p_q_bf, *p_qcha1_bf, *p_k_bf, *p_vbuf_bf, *p_vproj_bf, *p_obuf_bf, *p_xn2_bf, *p_h_bf;
    __nv_bfloat16 *p_wq_t, *p_wk_t, *p_wv_t, *p_wproj_t, *p_w1_t, *p_w2_t;
    cudaGetSymbolAddress((void**)&p_xw_bf, g_xw_bf);
    cudaGetSymbolAddress((void**)&p_q_bf, g_q_bf);
    cudaGetSymbolAddress((void**)&p_qcha1_bf, g_qcha1_bf);
    cudaGetSymbolAddress((void**)&p_k_bf, g_k_bf);
    cudaGetSymbolAddress((void**)&p_vbuf_bf, g_vbuf_bf);
    cudaGetSymbolAddress((void**)&p_vproj_bf, g_vproj_bf);
    cudaGetSymbolAddress((void**)&p_obuf_bf, g_obuf_bf);
    cudaGetSymbolAddress((void**)&p_xn2_bf, g_xn2_bf);
    cudaGetSymbolAddress((void**)&p_h_bf, g_h_bf);
    cudaGetSymbolAddress((void**)&p_wq_t, g_wq_t);
    cudaGetSymbolAddress((void**)&p_wk_t, g_wk_t);
    cudaGetSymbolAddress((void**)&p_wv_t, g_wv_t);
    cudaGetSymbolAddress((void**)&p_wproj_t, g_wproj_t);
    cudaGetSymbolAddress((void**)&p_w1_t, g_w1_t);
    cudaGetSymbolAddress((void**)&p_w2_t, g_w2_t);

    cudaFuncSetAttribute(gemm_bf16_kernel<0,1,0,0>, cudaFuncAttributeMaxDynamicSharedMemorySize, GEMM_SMEM);
    cudaFuncSetAttribute(gemm_bf16_kernel<0,0,1,0>, cudaFuncAttributeMaxDynamicSharedMemorySize, GEMM_SMEM);
    cudaFuncSetAttribute(gemm_bf16_kernel<0,1,0,1>, cudaFuncAttributeMaxDynamicSharedMemorySize, GEMM_SMEM);
    cudaFuncSetAttribute(gemm_bf16_kernel<1,0,1,0>, cudaFuncAttributeMaxDynamicSharedMemorySize, GEMM_SMEM);
    cudaFuncSetAttribute(topk_warp_kernel, cudaFuncAttributeMaxDynamicSharedMemorySize, TOPK_SMEM);

    // 0) all weight transposes in one launch
    wtrans_all_kernel<<<720, dim3(32, 8)>>>(wq, p_wq_t, wk, p_wk_t, wv, p_wv_t,
                                            wproj, p_wproj_t, w1, p_w1_t, w2, p_w2_t);
    // 1) LN1 + window partition (warp per row)
    ln1_warp_kernel<<<ROWS/8, 256>>>(x, norm1_g, norm1_b);
    // 2) q = xw @ wq + bq -> g_q_bf (bf16)
    gemm_bf16_kernel<0,0,1,0><<<dim3(CC/128, ROWS/128), 256, GEMM_SMEM>>>(
        p_xw_bf, p_wq_t, bq, nullptr, nullptr, p_q_bf, ROWS, CC, CC);
    // 3) top-k + gathers (warp per unit)
    topk_warp_kernel<<<BN/8, 256, TOPK_SMEM>>>(wch, bch);
    // 4) k = qcha1 @ wk + bk -> g_k_bf
    gemm_bf16_kernel<0,0,1,0><<<dim3((CC/2)/128, ROWS/128), 256, GEMM_SMEM>>>(
        p_qcha1_bf, p_wk_t, bk, nullptr, nullptr, p_k_bf, ROWS, CC/2, CC/2);
    // 5) v = vbuf @ wv + bv -> g_vproj_bf
    gemm_bf16_kernel<0,0,1,0><<<dim3(CC/128, MV/128), 256, GEMM_SMEM>>>(
        p_vbuf_bf, p_wv_t, bv, nullptr, nullptr, p_vproj_bf, MV, CC, CC);
    // 6) attention (warp per unit) -> g_obuf_bf
    attn_warp_kernel<<<BN/8, 256>>>(rpb);
    // 7) proj + window reverse + residual -> d_out (fused)
    gemm_bf16_kernel<0,1,0,1><<<dim3(CC/128, ROWS/128), 256, GEMM_SMEM>>>(
        p_obuf_bf, p_wproj_t, bproj, x, out, nullptr, ROWS, CC, CC);
    // 8) LN2(d_out) -> g_xn2_bf (warp per row)
    ln2_warp_kernel<<<ROWS/8, 256>>>(out, norm2_g, norm2_b);
    // 9) h = gelu(xn2 @ w1 + b1) -> g_h_bf (bf16 only)
    gemm_bf16_kernel<1,0,1,0><<<dim3(MLPH/128, ROWS/128), 256, GEMM_SMEM>>>(
        p_xn2_bf, p_w1_t, b1, nullptr, nullptr, p_h_bf, ROWS, CC, MLPH);
    // 10) out = out + h @ w2 + b2
    gemm_bf16_kernel<0,1,0,0><<<dim3(CC/128, ROWS/128), 256, GEMM_SMEM>>>(
        p_h_bf, p_w2_t, b2, out, out, nullptr, ROWS, MLPH, CC);
}

// round 15
// speedup vs baseline: 1.1081x; 1.1081x over previous
#include <cuda_runtime.h>
#include <cuda_bf16.h>
#include <math.h>
#include <stdint.h>

// ---------------- problem constants ----------------
#define BB   32
#define HH   56
#define WW   56
#define CC   256
#define WS   7
#define NH   8
#define HD   32
#define KCH  16
#define KSPT 28
#define NT   49          // tokens per window
#define MLPH 1024
#define LL   (HH*WW)     // 3136
#define ROWS (BB*LL)     // 100352
#define BW   2048        // windows
#define BN   (BW*NH)     // 16384
#define MV   (BW*KSPT)   // 57344 (v rows)
#define SCALE_F 0.17677669529663687f   // 32^-0.5

// ---------------- static scratch (no allocations allowed) ----------------
__device__ __nv_bfloat16 g_xw_bf[ROWS*CC];        // LN1 windowed (bf16) -> q gemm A
__device__ __nv_bfloat16 g_q_bf[ROWS*CC];         // q bf16 (topk reads)
__device__ __nv_bfloat16 g_qcha1_bf[BW*NT*(CC/2)];// channel-gathered q (bf16)
__device__ __nv_bfloat16 g_k_bf[ROWS*(CC/2)];     // k bf16 (attn reads)
__device__ __nv_bfloat16 g_vbuf_bf[MV*CC];        // gathered v input (bf16)
__device__ __nv_bfloat16 g_vproj_bf[MV*CC];       // v projected bf16 (attn reads)
__device__ __nv_bfloat16 g_obuf_bf[ROWS*CC];      // attn out (bf16) -> proj gemm A
__device__ __nv_bfloat16 g_xn2_bf[ROWS*CC];       // LN2 out (bf16) -> mlp1 A
__device__ __nv_bfloat16 g_h_bf[(size_t)ROWS*MLPH]; // mlp hidden (bf16)
__device__ int           g_sidx[BN*KSPT];
// transposed bf16 weights (N-major, K contiguous)
__device__ __nv_bfloat16 g_wq_t[CC*CC];
__device__ __nv_bfloat16 g_wk_t[(CC/2)*(CC/2)];
__device__ __nv_bfloat16 g_wv_t[CC*CC];
__device__ __nv_bfloat16 g_wproj_t[CC*CC];
__device__ __nv_bfloat16 g_w1_t[CC*MLPH];
__device__ __nv_bfloat16 g_w2_t[MLPH*CC];

// ---------------- small helpers ----------------
__device__ __forceinline__ float gelu_exact(float x) {
    return 0.5f * x * (1.0f + erff(x * 0.70710678118654752f));
}

__device__ __forceinline__ uint32_t smem_u32(const void* p) {
    return (uint32_t)__cvta_generic_to_shared(p);
}
__device__ __forceinline__ void cp_async16(uint32_t smem_dst, const void* gmem_src) {
    asm volatile("cp.async.ca.shared.global [%0], [%1], 16;\n" :: "r"(smem_dst), "l"(gmem_src));
}
#define CP_COMMIT()  asm volatile("cp.async.commit_group;\n" ::: "memory")
#define CP_WAIT(n)   asm volatile("cp.async.wait_group %0;\n" :: "n"(n) : "memory")

__device__ __forceinline__ void mma_bf16(float c[4], const uint32_t a[4], const uint32_t b[2]) {
    asm volatile(
        "mma.sync.aligned.m16n8k16.row.col.f32.bf16.bf16.f32 "
        "{%0,%1,%2,%3},{%4,%5,%6,%7},{%8,%9},{%0,%1,%2,%3};"
        : "+f"(c[0]), "+f"(c[1]), "+f"(c[2]), "+f"(c[3])
        : "r"(a[0]), "r"(a[1]), "r"(a[2]), "r"(a[3]), "r"(b[0]), "r"(b[1]));
}

__device__ __forceinline__ void ldsm_x4(uint32_t r[4], uint32_t addr) {
    asm volatile("ldmatrix.sync.aligned.m8n8.x4.shared.b16 {%0,%1,%2,%3}, [%4];"
        : "=r"(r[0]), "=r"(r[1]), "=r"(r[2]), "=r"(r[3]) : "r"(addr));
}
__device__ __forceinline__ void ldsm_x2(uint32_t r[2], uint32_t addr) {
    asm volatile("ldmatrix.sync.aligned.m8n8.x2.shared.b16 {%0,%1}, [%2];"
        : "=r"(r[0]), "=r"(r[1]) : "r"(addr));
}

// window-layout row -> (B, H*W) row
__device__ __forceinline__ int winrev_row(int wr) {
    int widx = wr / NT, token = wr % NT;
    int b = widx >> 6, rem = widx & 63;
    int wh = rem >> 3, ww = rem & 7;
    int h = wh * WS + token / WS;
    int w = ww * WS + token % WS;
    return b * LL + h * WW + w;
}

// ---------------- fused weight transpose+convert (all 6 weights, 1 launch) ----------------
__global__ void wtrans_all_kernel(
    const float* __restrict__ wq, __nv_bfloat16* __restrict__ wqt,
    const float* __restrict__ wk, __nv_bfloat16* __restrict__ wkt,
    const float* __restrict__ wv, __nv_bfloat16* __restrict__ wvt,
    const float* __restrict__ wp, __nv_bfloat16* __restrict__ wpt,
    const float* __restrict__ w1, __nv_bfloat16* __restrict__ w1t,
    const float* __restrict__ w2, __nv_bfloat16* __restrict__ w2t) {
    __shared__ float t[32][33];
    int bid = blockIdx.x;
    const float* W; __nv_bfloat16* Wt; int K, N, local;
    if      (bid < 64)  { W = wq; Wt = wqt; K = 256;  N = 256;  local = bid; }
    else if (bid < 80)  { W = wk; Wt = wkt; K = 128;  N = 128;  local = bid - 64; }
    else if (bid < 144) { W = wv; Wt = wvt; K = 256;  N = 256;  local = bid - 80; }
    else if (bid < 208) { W = wp; Wt = wpt; K = 256;  N = 256;  local = bid - 144; }
    else if (bid < 464) { W = w1; Wt = w1t; K = 256;  N = 1024; local = bid - 208; }
    else                { W = w2; Wt = w2t; K = 1024; N = 256;  local = bid - 464; }
    int tpx = N >> 5;
    int txi = local % tpx, tyi = local / tpx;
    int k0 = tyi * 32, n0 = txi * 32;
    int tx = threadIdx.x, ty = threadIdx.y;   // 32 x 8
    for (int i = ty; i < 32; i += 8) t[i][tx] = W[(size_t)(k0 + i) * N + n0 + tx];
    __syncthreads();
    for (int i = ty; i < 32; i += 8)
        Wt[(size_t)(n0 + i) * K + k0 + tx] = __float2bfloat16(t[tx][i]);
}

// ---------------- bf16 HMMA GEMM: D = act(A@W + bias) [+res], optional winrev remap ----------------
#define TSTR 72
#define TBUF (128*TSTR)
#define GEMM_SMEM (4*TBUF*2)   // 73728 bytes (2-stage: keeps 2 CTAs/SM)

template<int ACT, int OUTF32, int OUTBF, int WREV>
__global__ void __launch_bounds__(256, 2)
gemm_bf16_kernel(const __nv_bfloat16* __restrict__ A, const __nv_bfloat16* __restrict__ Bt,
                 const float* __restrict__ bias, const float* __restrict__ res,
                 float* __restrict__ D, __nv_bfloat16* __restrict__ Dbf,
                 int M, int Kt, int Ncols) {
    extern __shared__ __nv_bfloat16 sm[];
    __nv_bfloat16* As[2] = { sm, sm + TBUF };
    __nv_bfloat16* Bs[2] = { sm + 2*TBUF, sm + 3*TBUF };

    int tid = threadIdx.x;
    int warp = tid >> 5, lane = tid & 31;
    int g = lane >> 2, tig = lane & 3;
    int wm = warp >> 2, wn = warp & 3;   // 2 x 4 warp grid
    int bm = blockIdx.y * 128, bn = blockIdx.x * 128;

    // ldmatrix per-lane byte offsets (within a tile buffer)
    uint32_t a_off = ((uint32_t)(wm*64 + (lane & 15)) * TSTR + (lane >> 4) * 8) * 2;
    uint32_t b_off = ((uint32_t)(wn*32 + (lane & 7)) * TSTR + ((lane >> 3) & 1) * 8) * 2;

    float acc[4][4][4];
    #pragma unroll
    for (int mi = 0; mi < 4; mi++)
        #pragma unroll
        for (int ni = 0; ni < 4; ni++)
            #pragma unroll
            for (int j = 0; j < 4; j++) acc[mi][ni][j] = 0.0f;

    int T = Kt >> 6;

    auto issue = [&](int t, int buf) {
        int k0 = t << 6;
        #pragma unroll
        for (int i = 0; i < 4; i++) {
            int idx = tid + i * 256;
            int r = idx >> 3, q = idx & 7;
            cp_async16(smem_u32(&As[buf][r * TSTR + q * 8]),
                       A + (size_t)(bm + r) * Kt + k0 + q * 8);
        }
        #pragma unroll
        for (int i = 0; i < 4; i++) {
            int idx = tid + i * 256;
            int r = idx >> 3, q = idx & 7;
            cp_async16(smem_u32(&Bs[buf][r * TSTR + q * 8]),
                       Bt + (size_t)(bn + r) * Kt + k0 + q * 8);
        }
        CP_COMMIT();
    };

    issue(0, 0);

    for (int t = 0; t < T; t++) {
        int buf = t & 1;
        if (t + 1 < T) {
            issue(t + 1, buf ^ 1);
            CP_WAIT(1);
        } else {
            CP_WAIT(0);
        }
        __syncthreads();

        uint32_t as_base = smem_u32(As[buf]) + a_off;
        uint32_t bs_base = smem_u32(Bs[buf]) + b_off;

        #pragma unroll
        for (int kk = 0; kk < 64; kk += 16) {
            uint32_t af[4][4], bfr[4][2];
            #pragma unroll
            for (int mi = 0; mi < 4; mi++)
                ldsm_x4(af[mi], as_base + (uint32_t)(mi*16*TSTR + kk) * 2);
            #pragma unroll
            for (int ni = 0; ni < 4; ni++)
                ldsm_x2(bfr[ni], bs_base + (uint32_t)(ni*8*TSTR + kk) * 2);
            #pragma unroll
            for (int mi = 0; mi < 4; mi++)
                #pragma unroll
                for (int ni = 0; ni < 4; ni++)
                    mma_bf16(acc[mi][ni], af[mi], bfr[ni]);
        }
        __syncthreads();
    }

    #pragma unroll
    for (int mi = 0; mi < 4; mi++) {
        int r0 = bm + wm*64 + mi*16 + g;
        int r1 = r0 + 8;
        int o0 = WREV ? winrev_row(r0) : r0;
        int o1 = WREV ? winrev_row(r1) : r1;
        #pragma unroll
        for (int ni = 0; ni < 4; ni++) {
            int col = bn + wn*32 + ni*8 + tig*2;
            const float2 bi = *reinterpret_cast<const float2*>(bias + col);
            float v0 = acc[mi][ni][0] + bi.x;
            float v1 = acc[mi][ni][1] + bi.y;
            float v2 = acc[mi][ni][2] + bi.x;
            float v3 = acc[mi][ni][3] + bi.y;
            if (ACT == 1) { v0 = gelu_exact(v0); v1 = gelu_exact(v1); v2 = gelu_exact(v2); v3 = gelu_exact(v3); }
            size_t i0 = (size_t)o0 * Ncols + col;
            size_t i1 = (size_t)o1 * Ncols + col;
            if (res) {
                const float2 ra = *reinterpret_cast<const float2*>(res + i0);
                const float2 rb = *reinterpret_cast<const float2*>(res + i1);
                v0 += ra.x; v1 += ra.y; v2 += rb.x; v3 += rb.y;
            }
            if (OUTF32) {
                *reinterpret_cast<float2*>(D + i0) = make_float2(v0, v1);
                *reinterpret_cast<float2*>(D + i1) = make_float2(v2, v3);
            }
            if (OUTBF) {
                __nv_bfloat162 p0 = __floats2bfloat162_rn(v0, v1);
                __nv_bfloat162 p1 = __floats2bfloat162_rn(v2, v3);
                *reinterpret_cast<__nv_bfloat162*>(Dbf + i0) = p0;
                *reinterpret_cast<__nv_bfloat162*>(Dbf + i1) = p1;
            }
        }
    }
}

// ---------------- warp-per-row LN1 + window partition (bf16 out) ----------------
__global__ void __launch_bounds__(256)
ln1_warp_kernel(const float* __restrict__ x,
                const float* __restrict__ gam, const float* __restrict__ bet) {
    int wid = threadIdx.x >> 5, lane = threadIdx.x & 31;
    int row = blockIdx.x * 8 + wid;
    const float* xr = x + (size_t)row * CC;
    float4 a = *reinterpret_cast<const float4*>(xr + lane*4);
    float4 b = *reinterpret_cast<const float4*>(xr + 128 + lane*4);
    float s = a.x+a.y+a.z+a.w + b.x+b.y+b.z+b.w;
    float s2 = a.x*a.x+a.y*a.y+a.z*a.z+a.w*a.w + b.x*b.x+b.y*b.y+b.z*b.z+b.w*b.w;
    #pragma unroll
    for (int o = 16; o > 0; o >>= 1) {
        s  += __shfl_xor_sync(0xffffffffu, s,  o);
        s2 += __shfl_xor_sync(0xffffffffu, s2, o);
    }
    float mu = s * (1.0f/CC);
    float rstd = rsqrtf(s2 * (1.0f/CC) - mu*mu + 1e-5f);
    int bidx = row / LL, l = row % LL;
    int h = l / WW, w = l % WW;
    int widx = (bidx*8 + h/WS)*8 + (w/WS);
    int token = (h%WS)*WS + (w%WS);
    __nv_bfloat16* dst = g_xw_bf + ((size_t)widx*NT + token)*CC;
    float4 g0 = *reinterpret_cast<const float4*>(gam + lane*4);
    float4 g1 = *reinterpret_cast<const float4*>(gam + 128 + lane*4);
    float4 b0 = *reinterpret_cast<const float4*>(bet + lane*4);
    float4 b1 = *reinterpret_cast<const float4*>(bet + 128 + lane*4);
    __nv_bfloat162 p0 = __floats2bfloat162_rn((a.x-mu)*rstd*g0.x+b0.x, (a.y-mu)*rstd*g0.y+b0.y);
    __nv_bfloat162 p1 = __floats2bfloat162_rn((a.z-mu)*rstd*g0.z+b0.z, (a.w-mu)*rstd*g0.w+b0.w);
    __nv_bfloat162 p2 = __floats2bfloat162_rn((b.x-mu)*rstd*g1.x+b1.x, (b.y-mu)*rstd*g1.y+b1.y);
    __nv_bfloat162 p3 = __floats2bfloat162_rn((b.z-mu)*rstd*g1.z+b1.z, (b.w-mu)*rstd*g1.w+b1.w);
    uint2 u0; u0.x = *reinterpret_cast<uint32_t*>(&p0); u0.y = *reinterpret_cast<uint32_t*>(&p1);
    uint2 u1; u1.x = *reinterpret_cast<uint32_t*>(&p2); u1.y = *reinterpret_cast<uint32_t*>(&p3);
    *reinterpret_cast<uint2*>(dst + lane*4) = u0;
    *reinterpret_cast<uint2*>(dst + 128 + lane*4) = u1;
}

// ---------------- warp-per-row LN2 (bf16 out, linear) ----------------
__global__ void __launch_bounds__(256)
ln2_warp_kernel(const float* __restrict__ x,
                const float* __restrict__ gam, const float* __restrict__ bet) {
    int wid = threadIdx.x >> 5, lane = threadIdx.x & 31;
    int row = blockIdx.x * 8 + wid;
    const float* xr = x + (size_t)row * CC;
    float4 a = *reinterpret_cast<const float4*>(xr + lane*4);
    float4 b = *reinterpret_cast<const float4*>(xr + 128 + lane*4);
    float s = a.x+a.y+a.z+a.w + b.x+b.y+b.z+b.w;
    float s2 = a.x*a.x+a.y*a.y+a.z*a.z+a.w*a.w + b.x*b.x+b.y*b.y+b.z*b.z+b.w*b.w;
    #pragma unroll
    for (int o = 16; o > 0; o >>= 1) {
        s  += __shfl_xor_sync(0xffffffffu, s,  o);
        s2 += __shfl_xor_sync(0xffffffffu, s2, o);
    }
    float mu = s * (1.0f/CC);
    float rstd = rsqrtf(s2 * (1.0f/CC) - mu*mu + 1e-5f);
    __nv_bfloat16* dst = g_xn2_bf + (size_t)row * CC;
    float4 g0 = *reinterpret_cast<const float4*>(gam + lane*4);
    float4 g1 = *reinterpret_cast<const float4*>(gam + 128 + lane*4);
    float4 b0 = *reinterpret_cast<const float4*>(bet + lane*4);
    float4 b1 = *reinterpret_cast<const float4*>(bet + 128 + lane*4);
    __nv_bfloat162 p0 = __floats2bfloat162_rn((a.x-mu)*rstd*g0.x+b0.x, (a.y-mu)*rstd*g0.y+b0.y);
    __nv_bfloat162 p1 = __floats2bfloat162_rn((a.z-mu)*rstd*g0.z+b0.z, (a.w-mu)*rstd*g0.w+b0.w);
    __nv_bfloat162 p2 = __floats2bfloat162_rn((b.x-mu)*rstd*g1.x+b1.x, (b.y-mu)*rstd*g1.y+b1.y);
    __nv_bfloat162 p3 = __floats2bfloat162_rn((b.z-mu)*rstd*g1.z+b1.z, (b.w-mu)*rstd*g1.w+b1.w);
    uint2 u0; u0.x = *reinterpret_cast<uint32_t*>(&p0); u0.y = *reinterpret_cast<uint32_t*>(&p1);
    uint2 u1; u1.x = *reinterpret_cast<uint32_t*>(&p2); u1.y = *reinterpret_cast<uint32_t*>(&p3);
    *reinterpret_cast<uint2*>(dst + lane*4) = u0;
    *reinterpret_cast<uint2*>(dst + 128 + lane*4) = u1;
}

// ---------------- warp-per-(window,head) top-k + gathers (bf16 q) ----------------
#define TKQT  (NT*33)
#define TKREG (TKQT + 49 + 28 + 2)
#define TOPK_SMEM (8*TKREG*4)

__global__ void __launch_bounds__(256)
topk_warp_kernel(const float* __restrict__ wch, const float* __restrict__ bch) {
    extern __shared__ float tsm[];
    int wid = threadIdx.x >> 5, lane = threadIdx.x & 31;
    float* qt  = tsm + wid * TKREG;
    float* tm  = qt + TKQT;
    int*   sidx = (int*)(tm + 49);
    int bn = blockIdx.x * 8 + wid;
    int widx = bn >> 3, nh = bn & 7;

    const __nv_bfloat16* base = g_q_bf + (size_t)widx*NT*CC + nh*HD + lane;
    float cs = 0.0f, cm = -1e30f;
    #pragma unroll
    for (int t = 0; t < NT; t++) {
        float v = __bfloat162float(base[(size_t)t*CC]);
        qt[t*33 + lane] = v;
        cs += v; cm = fmaxf(cm, v);
    }
    float cmean = cs * (1.0f/NT);
    __syncwarp();

    for (int t = lane; t < NT; t += 32) {
        float s = 0.0f;
        #pragma unroll
        for (int hd = 0; hd < HD; hd++) s += qt[t*33 + hd];
        tm[t] = s * (1.0f/HD);
    }
    __syncwarp();

    float sc = bch[lane];
    #pragma unroll
    for (int i = 0; i < HD; i++) {
        float cmi = __shfl_sync(0xffffffffu, cmean, i);
        float cxi = __shfl_sync(0xffffffffu, cm, i);
        sc += cmi * wch[i*HD + lane] + cxi * wch[(HD+i)*HD + lane];
    }
    sc = gelu_exact(sc);

    int cnt = 0;
    #pragma unroll
    for (int j = 0; j < HD; j++) {
        float sj = __shfl_sync(0xffffffffu, sc, j);
        cnt += (sj > sc) || (sj == sc && j < lane);
    }
    int cflag = cnt < KCH;
    unsigned cmask = __ballot_sync(0xffffffffu, cflag);
    int cpos = __popc(cmask & ((1u << lane) - 1u));

    float t0v = tm[lane];
    float t1v = (lane + 32 < NT) ? tm[lane + 32] : -1e30f;
    int scnt0 = 0, scnt1 = 0;
    #pragma unroll
    for (int j = 0; j < NT; j++) {
        float tj = tm[j];
        scnt0 += (tj > t0v) || (tj == t0v && j < lane);
        scnt1 += (tj > t1v) || (tj == t1v && j < lane + 32);
    }
    int sflag0 = scnt0 < KSPT;
    int sflag1 = (lane + 32 < NT) && (scnt1 < KSPT);
    unsigned m0 = __ballot_sync(0xffffffffu, sflag0);
    unsigned m1 = __ballot_sync(0xffffffffu, sflag1);
    if (sflag0) sidx[__popc(m0 & ((1u << lane) - 1u))] = lane;
    if (sflag1) sidx[__popc(m0) + __popc(m1 & ((1u << lane) - 1u))] = lane + 32;
    __syncwarp();

    if (cflag) {
        __nv_bfloat16* dst = g_qcha1_bf + (size_t)widx*NT*(CC/2) + nh*KCH + cpos;
        #pragma unroll
        for (int t = 0; t < NT; t++)
            dst[(size_t)t*(CC/2)] = __float2bfloat16(qt[t*33 + lane]);
    }
    {
        __nv_bfloat16* dst = g_vbuf_bf + (size_t)widx*KSPT*CC + nh*HD + lane;
        #pragma unroll
        for (int s = 0; s < KSPT; s++) {
            int t = sidx[s];
            dst[(size_t)s*CC] = __float2bfloat16(qt[t*33 + lane]);
        }
    }
    if (lane < KSPT) g_sidx[bn*KSPT + lane] = sidx[lane];
}

// ---------------- warp-per-(window,head) attention ----------------
__global__ void __launch_bounds__(256)
attn_warp_kernel(const float* __restrict__ rpb) {
    __shared__ float khs[8][NT*KCH];
    int wid = threadIdx.x >> 5, lane = threadIdx.x & 31;
    int bn = blockIdx.x * 8 + wid;
    int widx = bn >> 3, nh = bn & 7;
    float* kh = khs[wid];

    for (int t = lane; t < NT; t += 32) {
        const __nv_bfloat16* src = g_k_bf + ((size_t)widx*NT + t)*(CC/2) + nh*KCH;
        uint4 a = *reinterpret_cast<const uint4*>(src);
        uint4 b = *reinterpret_cast<const uint4*>(src + 8);
        const __nv_bfloat16* pa = reinterpret_cast<const __nv_bfloat16*>(&a);
        const __nv_bfloat16* pb = reinterpret_cast<const __nv_bfloat16*>(&b);
        #pragma unroll
        for (int j = 0; j < 8; j++) kh[t*KCH + j]     = __bfloat162float(pa[j]);
        #pragma unroll
        for (int j = 0; j < 8; j++) kh[t*KCH + 8 + j] = __bfloat162float(pb[j]);
    }

    float vreg[KSPT];
    #pragma unroll
    for (int s = 0; s < KSPT; s++)
        vreg[s] = __bfloat162float(g_vproj_bf[((size_t)widx*KSPT + s)*CC + nh*HD + lane]);

    float qa[KCH];
    int r2 = 0, c2 = 0;
    if (lane < KSPT) {
        int t2 = g_sidx[bn*KSPT + lane];
        r2 = t2 / WS; c2 = t2 % WS;
        const __nv_bfloat16* src = g_qcha1_bf + ((size_t)widx*NT + t2)*(CC/2) + nh*KCH;
        uint4 a = *reinterpret_cast<const uint4*>(src);
        uint4 b = *reinterpret_cast<const uint4*>(src + 8);
        const __nv_bfloat16* pa = reinterpret_cast<const __nv_bfloat16*>(&a);
        const __nv_bfloat16* pb = reinterpret_cast<const __nv_bfloat16*>(&b);
        #pragma unroll
        for (int j = 0; j < 8; j++) qa[j]     = __bfloat162float(pa[j]) * SCALE_F;
        #pragma unroll
        for (int j = 0; j < 8; j++) qa[8 + j] = __bfloat162float(pb[j]) * SCALE_F;
    } else {
        #pragma unroll
        for (int j = 0; j < KCH; j++) qa[j] = 0.0f;
    }
    __syncwarp();

    __nv_bfloat16* obase = g_obuf_bf + (size_t)widx*NT*CC + nh*HD + lane;
    const float inv_kspt = 1.0f / KSPT;
    for (int t = 0; t < NT; t++) {
        float sum = 0.0f;
        #pragma unroll
        for (int j = 0; j < KCH; j++) sum += kh[t*KCH + j] * qa[j];
        int rt = t / WS, ct = t % WS;
        int rel = (rt - r2 + WS - 1) * (2*WS - 1) + (ct - c2 + WS - 1);
        float at = sum + rpb[rel*NH + nh];
        if (lane >= KSPT) at = -1e30f;
        float m = at;
        #pragma unroll
        for (int o = 16; o > 0; o >>= 1) m = fmaxf(m, __shfl_xor_sync(0xffffffffu, m, o));
        float araw = (lane < KSPT) ? at : 0.0f;
        #pragma unroll
        for (int o = 16; o > 0; o >>= 1) araw += __shfl_xor_sync(0xffffffffu, araw, o);
        float gate = 1.0f / (1.0f + expf(-araw * inv_kspt));
        float e = expf(at - m);
        float es = e;
        #pragma unroll
        for (int o = 16; o > 0; o >>= 1) es += __shfl_xor_sync(0xffffffffu, es, o);
        float p = e * (gate / es);
        float acc = 0.0f;
        #pragma unroll
        for (int s = 0; s < KSPT; s++)
            acc += __shfl_sync(0xffffffffu, p, s) * vreg[s];
        obase[(size_t)t*CC] = __float2bfloat16(acc);
    }
}

// ---------------- launch ----------------
extern "C" void kernel_launch(void* const* d_in, const int* in_sizes, int n_in,
                              void* d_out, int out_size) {
    const float* x       = (const float*)d_in[0];
    const float* norm1_g = (const float*)d_in[1];
    const float* norm1_b = (const float*)d_in[2];
    const float* wq      = (const float*)d_in[3];
    const float* bq      = (const float*)d_in[4];
    const float* wk      = (const float*)d_in[5];
    const float* bk      = (const float*)d_in[6];
    const float* wv      = (const float*)d_in[7];
    const float* bv      = (const float*)d_in[8];
    const float* wproj   = (const float*)d_in[9];
    const float* bproj   = (const float*)d_in[10];
    const float* wch     = (const float*)d_in[11];
    const float* bch     = (const float*)d_in[12];
    const float* rpb     = (const float*)d_in[13];
    const float* norm2_g = (const float*)d_in[14];
    const float* norm2_b = (const float*)d_in[15];
    const float* w1      = (const float*)d_in[16];
    const float* b1      = (const float*)d_in[17];
    const float* w2      = (const float*)d_in[18];
    const float* b2      = (const float*)d_in[19];
    float* out = (float*)d_out;

    __nv_bfloat16 *p_xw_bf, *p_q_bf, *p_qcha1_bf, *p_k_bf, *p_vbuf_bf, *p_vproj_bf, *p_obuf_bf, *p_xn2_bf, *p_h_bf;
    __nv_bfloat16 *p_wq_t, *p_wk_t, *p_wv_t, *p_wproj_t, *p_w1_t, *p_w2_t;
    cudaGetSymbolAddress((void**)&p_xw_bf, g_xw_bf);
    cudaGetSymbolAddress((void**)&p_q_bf, g_q_bf);
    cudaGetSymbolAddress((void**)&p_qcha1_bf, g_qcha1_bf);
    cudaGetSymbolAddress((void**)&p_k_bf, g_k_bf);
    cudaGetSymbolAddress((void**)&p_vbuf_bf, g_vbuf_bf);
    cudaGetSymbolAddress((void**)&p_vproj_bf, g_vproj_bf);
    cudaGetSymbolAddress((void**)&p_obuf_bf, g_obuf_bf);
    cudaGetSymbolAddress((void**)&p_xn2_bf, g_xn2_bf);
    cudaGetSymbolAddress((void**)&p_h_bf, g_h_bf);
    cudaGetSymbolAddress((void**)&p_wq_t, g_wq_t);
    cudaGetSymbolAddress((void**)&p_wk_t, g_wk_t);
    cudaGetSymbolAddress((void**)&p_wv_t, g_wv_t);
    cudaGetSymbolAddress((void**)&p_wproj_t, g_wproj_t);
    cudaGetSymbolAddress((void**)&p_w1_t, g_w1_t);
    cudaGetSymbolAddress((void**)&p_w2_t, g_w2_t);

    cudaFuncSetAttribute(gemm_bf16_kernel<0,1,0,0>, cudaFuncAttributeMaxDynamicSharedMemorySize, GEMM_SMEM);
    cudaFuncSetAttribute(gemm_bf16_kernel<0,0,1,0>, cudaFuncAttributeMaxDynamicSharedMemorySize, GEMM_SMEM);
    cudaFuncSetAttribute(gemm_bf16_kernel<0,1,0,1>, cudaFuncAttributeMaxDynamicSharedMemorySize, GEMM_SMEM);
    cudaFuncSetAttribute(gemm_bf16_kernel<1,0,1,0>, cudaFuncAttributeMaxDynamicSharedMemorySize, GEMM_SMEM);
    cudaFuncSetAttribute(topk_warp_kernel, cudaFuncAttributeMaxDynamicSharedMemorySize, TOPK_SMEM);

    // 0) all weight transposes in one launch
    wtrans_all_kernel<<<720, dim3(32, 8)>>>(wq, p_wq_t, wk, p_wk_t, wv, p_wv_t,
                                            wproj, p_wproj_t, w1, p_w1_t, w2, p_w2_t);
    // 1) LN1 + window partition (warp per row)
    ln1_warp_kernel<<<ROWS/8, 256>>>(x, norm1_g, norm1_b);
    // 2) q = xw @ wq + bq -> g_q_bf (bf16)
    gemm_bf16_kernel<0,0,1,0><<<dim3(CC/128, ROWS/128), 256, GEMM_SMEM>>>(
        p_xw_bf, p_wq_t, bq, nullptr, nullptr, p_q_bf, ROWS, CC, CC);
    // 3) top-k + gathers (warp per unit)
    topk_warp_kernel<<<BN/8, 256, TOPK_SMEM>>>(wch, bch);
    // 4) k = qcha1 @ wk + bk -> g_k_bf
    gemm_bf16_kernel<0,0,1,0><<<dim3((CC/2)/128, ROWS/128), 256, GEMM_SMEM>>>(
        p_qcha1_bf, p_wk_t, bk, nullptr, nullptr, p_k_bf, ROWS, CC/2, CC/2);
    // 5) v = vbuf @ wv + bv -> g_vproj_bf
    gemm_bf16_kernel<0,0,1,0><<<dim3(CC/128, MV/128), 256, GEMM_SMEM>>>(
        p_vbuf_bf, p_wv_t, bv, nullptr, nullptr, p_vproj_bf, MV, CC, CC);
    // 6) attention (warp per unit) -> g_obuf_bf
    attn_warp_kernel<<<BN/8, 256>>>(rpb);
    // 7) proj + window reverse + residual -> d_out (fused)
    gemm_bf16_kernel<0,1,0,1><<<dim3(CC/128, ROWS/128), 256, GEMM_SMEM>>>(
        p_obuf_bf, p_wproj_t, bproj, x, out, nullptr, ROWS, CC, CC);
    // 8) LN2(d_out) -> g_xn2_bf (warp per row)
    ln2_warp_kernel<<<ROWS/8, 256>>>(out, norm2_g, norm2_b);
    // 9) h = gelu(xn2 @ w1 + b1) -> g_h_bf (bf16 only)
    gemm_bf16_kernel<1,0,1,0><<<dim3(MLPH/128, ROWS/128), 256, GEMM_SMEM>>>(
        p_xn2_bf, p_w1_t, b1, nullptr, nullptr, p_h_bf, ROWS, CC, MLPH);
    // 10) out = out + h @ w2 + b2
    gemm_bf16_kernel<0,1,0,0><<<dim3(CC/128, ROWS/128), 256, GEMM_SMEM>>>(
        p_h_bf, p_w2_t, b2, out, out, nullptr, ROWS, MLPH, CC);
}

// round 16
// speedup vs baseline: 1.1321x; 1.0217x over previous
#include <cuda_runtime.h>
#include <cuda_bf16.h>
#include <math.h>
#include <stdint.h>

// ---------------- problem constants ----------------
#define BB   32
#define HH   56
#define WW   56
#define CC   256
#define WS   7
#define NH   8
#define HD   32
#define KCH  16
#define KSPT 28
#define NT   49          // tokens per window
#define MLPH 1024
#define LL   (HH*WW)     // 3136
#define ROWS (BB*LL)     // 100352
#define BW   2048        // windows
#define BN   (BW*NH)     // 16384
#define MV   (BW*KSPT)   // 57344 (v rows)
#define SCALE_F 0.17677669529663687f   // 32^-0.5

// ---------------- static scratch (no allocations allowed) ----------------
__device__ __nv_bfloat16 g_xw_bf[ROWS*CC];        // LN1 windowed (bf16) -> q gemm A
__device__ __nv_bfloat16 g_q_bf[ROWS*CC];         // q bf16 (topk reads)
__device__ __nv_bfloat16 g_qcha1_bf[BW*NT*(CC/2)];// channel-gathered q (bf16)
__device__ __nv_bfloat16 g_k_bf[ROWS*(CC/2)];     // k bf16 (attn reads)
__device__ __nv_bfloat16 g_vbuf_bf[MV*CC];        // gathered v input (bf16)
__device__ __nv_bfloat16 g_vproj_bf[MV*CC];       // v projected bf16 (attn reads)
__device__ __nv_bfloat16 g_obuf_bf[ROWS*CC];      // attn out (bf16) -> proj gemm A
__device__ __nv_bfloat16 g_xn2_bf[ROWS*CC];       // LN2 out (bf16) -> mlp1 A
__device__ __nv_bfloat16 g_h_bf[(size_t)ROWS*MLPH]; // mlp hidden (bf16)
__device__ int           g_sidx[BN*KSPT];
// transposed bf16 weights (N-major, K contiguous)
__device__ __nv_bfloat16 g_wq_t[CC*CC];
__device__ __nv_bfloat16 g_wk_t[(CC/2)*(CC/2)];
__device__ __nv_bfloat16 g_wv_t[CC*CC];
__device__ __nv_bfloat16 g_wproj_t[CC*CC];
__device__ __nv_bfloat16 g_w1_t[CC*MLPH];
__device__ __nv_bfloat16 g_w2_t[MLPH*CC];

// ---------------- small helpers ----------------
__device__ __forceinline__ float gelu_exact(float x) {
    return 0.5f * x * (1.0f + erff(x * 0.70710678118654752f));
}

__device__ __forceinline__ uint32_t smem_u32(const void* p) {
    return (uint32_t)__cvta_generic_to_shared(p);
}
__device__ __forceinline__ void cp_async16(uint32_t smem_dst, const void* gmem_src) {
    asm volatile("cp.async.cg.shared.global [%0], [%1], 16;\n" :: "r"(smem_dst), "l"(gmem_src));
}
#define CP_COMMIT()  asm volatile("cp.async.commit_group;\n" ::: "memory")
#define CP_WAIT(n)   asm volatile("cp.async.wait_group %0;\n" :: "n"(n) : "memory")

__device__ __forceinline__ void mma_bf16(float c[4], const uint32_t a[4], const uint32_t b[2]) {
    asm volatile(
        "mma.sync.aligned.m16n8k16.row.col.f32.bf16.bf16.f32 "
        "{%0,%1,%2,%3},{%4,%5,%6,%7},{%8,%9},{%0,%1,%2,%3};"
        : "+f"(c[0]), "+f"(c[1]), "+f"(c[2]), "+f"(c[3])
        : "r"(a[0]), "r"(a[1]), "r"(a[2]), "r"(a[3]), "r"(b[0]), "r"(b[1]));
}

__device__ __forceinline__ void ldsm_x4(uint32_t r[4], uint32_t addr) {
    asm volatile("ldmatrix.sync.aligned.m8n8.x4.shared.b16 {%0,%1,%2,%3}, [%4];"
        : "=r"(r[0]), "=r"(r[1]), "=r"(r[2]), "=r"(r[3]) : "r"(addr));
}
__device__ __forceinline__ void ldsm_x2(uint32_t r[2], uint32_t addr) {
    asm volatile("ldmatrix.sync.aligned.m8n8.x2.shared.b16 {%0,%1}, [%2];"
        : "=r"(r[0]), "=r"(r[1]) : "r"(addr));
}

// window-layout row -> (B, H*W) row
__device__ __forceinline__ int winrev_row(int wr) {
    int widx = wr / NT, token = wr % NT;
    int b = widx >> 6, rem = widx & 63;
    int wh = rem >> 3, ww = rem & 7;
    int h = wh * WS + token / WS;
    int w = ww * WS + token % WS;
    return b * LL + h * WW + w;
}

// ---------------- GEMM tile body (device function) ----------------
#define TSTR 72
#define TBUF (128*TSTR)
#define GEMM_SMEM (4*TBUF*2)   // 73728 bytes (2-stage: keeps 2 CTAs/SM)

template<int ACT, int OUTF32, int OUTBF, int WREV>
__device__ __forceinline__ void gemm_tile(
    __nv_bfloat16* sm,
    const __nv_bfloat16* __restrict__ A, const __nv_bfloat16* __restrict__ Bt,
    const float* __restrict__ bias, const float* __restrict__ res,
    float* __restrict__ D, __nv_bfloat16* __restrict__ Dbf,
    int Kt, int Ncols, int bm, int bn) {
    __nv_bfloat16* As[2] = { sm, sm + TBUF };
    __nv_bfloat16* Bs[2] = { sm + 2*TBUF, sm + 3*TBUF };

    int tid = threadIdx.x;
    int warp = tid >> 5, lane = tid & 31;
    int g = lane >> 2, tig = lane & 3;
    int wm = warp >> 2, wn = warp & 3;   // 2 x 4 warp grid

    uint32_t a_off = ((uint32_t)(wm*64 + (lane & 15)) * TSTR + (lane >> 4) * 8) * 2;
    uint32_t b_off = ((uint32_t)(wn*32 + (lane & 7)) * TSTR + ((lane >> 3) & 1) * 8) * 2;

    float acc[4][4][4];
    #pragma unroll
    for (int mi = 0; mi < 4; mi++)
        #pragma unroll
        for (int ni = 0; ni < 4; ni++)
            #pragma unroll
            for (int j = 0; j < 4; j++) acc[mi][ni][j] = 0.0f;

    int T = Kt >> 6;

    auto issue = [&](int t, int buf) {
        int k0 = t << 6;
        #pragma unroll
        for (int i = 0; i < 4; i++) {
            int idx = tid + i * 256;
            int r = idx >> 3, q = idx & 7;
            cp_async16(smem_u32(&As[buf][r * TSTR + q * 8]),
                       A + (size_t)(bm + r) * Kt + k0 + q * 8);
        }
        #pragma unroll
        for (int i = 0; i < 4; i++) {
            int idx = tid + i * 256;
            int r = idx >> 3, q = idx & 7;
            cp_async16(smem_u32(&Bs[buf][r * TSTR + q * 8]),
                       Bt + (size_t)(bn + r) * Kt + k0 + q * 8);
        }
        CP_COMMIT();
    };

    issue(0, 0);

    for (int t = 0; t < T; t++) {
        int buf = t & 1;
        if (t + 1 < T) {
            issue(t + 1, buf ^ 1);
            CP_WAIT(1);
        } else {
            CP_WAIT(0);
        }
        __syncthreads();

        uint32_t as_base = smem_u32(As[buf]) + a_off;
        uint32_t bs_base = smem_u32(Bs[buf]) + b_off;

        #pragma unroll
        for (int kk = 0; kk < 64; kk += 16) {
            uint32_t af[4][4], bfr[4][2];
            #pragma unroll
            for (int mi = 0; mi < 4; mi++)
                ldsm_x4(af[mi], as_base + (uint32_t)(mi*16*TSTR + kk) * 2);
            #pragma unroll
            for (int ni = 0; ni < 4; ni++)
                ldsm_x2(bfr[ni], bs_base + (uint32_t)(ni*8*TSTR + kk) * 2);
            #pragma unroll
            for (int mi = 0; mi < 4; mi++)
                #pragma unroll
                for (int ni = 0; ni < 4; ni++)
                    mma_bf16(acc[mi][ni], af[mi], bfr[ni]);
        }
        __syncthreads();
    }

    #pragma unroll
    for (int mi = 0; mi < 4; mi++) {
        int r0 = bm + wm*64 + mi*16 + g;
        int r1 = r0 + 8;
        int o0 = WREV ? winrev_row(r0) : r0;
        int o1 = WREV ? winrev_row(r1) : r1;
        #pragma unroll
        for (int ni = 0; ni < 4; ni++) {
            int col = bn + wn*32 + ni*8 + tig*2;
            const float2 bi = *reinterpret_cast<const float2*>(bias + col);
            float v0 = acc[mi][ni][0] + bi.x;
            float v1 = acc[mi][ni][1] + bi.y;
            float v2 = acc[mi][ni][2] + bi.x;
            float v3 = acc[mi][ni][3] + bi.y;
            if (ACT == 1) { v0 = gelu_exact(v0); v1 = gelu_exact(v1); v2 = gelu_exact(v2); v3 = gelu_exact(v3); }
            size_t i0 = (size_t)o0 * Ncols + col;
            size_t i1 = (size_t)o1 * Ncols + col;
            if (res) {
                const float2 ra = *reinterpret_cast<const float2*>(res + i0);
                const float2 rb = *reinterpret_cast<const float2*>(res + i1);
                v0 += ra.x; v1 += ra.y; v2 += rb.x; v3 += rb.y;
            }
            if (OUTF32) {
                *reinterpret_cast<float2*>(D + i0) = make_float2(v0, v1);
                *reinterpret_cast<float2*>(D + i1) = make_float2(v2, v3);
            }
            if (OUTBF) {
                __nv_bfloat162 p0 = __floats2bfloat162_rn(v0, v1);
                __nv_bfloat162 p1 = __floats2bfloat162_rn(v2, v3);
                *reinterpret_cast<__nv_bfloat162*>(Dbf + i0) = p0;
                *reinterpret_cast<__nv_bfloat162*>(Dbf + i1) = p1;
            }
        }
    }
}

// ---------------- plain GEMM kernel wrapper ----------------
template<int ACT, int OUTF32, int OUTBF, int WREV>
__global__ void __launch_bounds__(256, 2)
gemm_bf16_kernel(const __nv_bfloat16* __restrict__ A, const __nv_bfloat16* __restrict__ Bt,
                 const float* __restrict__ bias, const float* __restrict__ res,
                 float* __restrict__ D, __nv_bfloat16* __restrict__ Dbf,
                 int M, int Kt, int Ncols) {
    extern __shared__ __nv_bfloat16 sm[];
    gemm_tile<ACT, OUTF32, OUTBF, WREV>(sm, A, Bt, bias, res, D, Dbf,
                                        Kt, Ncols, blockIdx.y * 128, blockIdx.x * 128);
}

// ---------------- merged k-GEMM + v-GEMM (wave merging) ----------------
#define KV_KBLKS (ROWS/128)          // 784
#define KV_TOTAL (KV_KBLKS + (MV/128)*2)  // 784 + 896 = 1680
__global__ void __launch_bounds__(256, 2)
kv_gemm_kernel(const __nv_bfloat16* __restrict__ qcha1, const __nv_bfloat16* __restrict__ wkt,
               const float* __restrict__ bk,
               const __nv_bfloat16* __restrict__ vbuf, const __nv_bfloat16* __restrict__ wvt,
               const float* __restrict__ bv,
               __nv_bfloat16* __restrict__ kout, __nv_bfloat16* __restrict__ vout) {
    extern __shared__ __nv_bfloat16 sm[];
    int bid = blockIdx.x;
    if (bid < KV_KBLKS) {
        gemm_tile<0,0,1,0>(sm, qcha1, wkt, bk, nullptr, nullptr, kout,
                           CC/2, CC/2, bid * 128, 0);
    } else {
        int j = bid - KV_KBLKS;
        gemm_tile<0,0,1,0>(sm, vbuf, wvt, bv, nullptr, nullptr, vout,
                           CC, CC, (j >> 1) * 128, (j & 1) * 128);
    }
}

// ---------------- merged wtrans + LN1 preamble ----------------
__device__ __forceinline__ void wtrans_tile(const float* W, __nv_bfloat16* Wt,
                                            int K, int N, int local) {
    __shared__ float t[32][33];
    int tx = threadIdx.x & 31, ty = threadIdx.x >> 5;   // 32 x 8
    int tpx = N >> 5;
    int txi = local % tpx, tyi = local / tpx;
    int k0 = tyi * 32, n0 = txi * 32;
    for (int i = ty; i < 32; i += 8) t[i][tx] = W[(size_t)(k0 + i) * N + n0 + tx];
    __syncthreads();
    for (int i = ty; i < 32; i += 8)
        Wt[(size_t)(n0 + i) * K + k0 + tx] = __float2bfloat16(t[tx][i]);
}

__device__ __forceinline__ void ln_row(const float* __restrict__ xr,
                                       const float* __restrict__ gam, const float* __restrict__ bet,
                                       __nv_bfloat16* __restrict__ dst, int lane) {
    float4 a = *reinterpret_cast<const float4*>(xr + lane*4);
    float4 b = *reinterpret_cast<const float4*>(xr + 128 + lane*4);
    float s = a.x+a.y+a.z+a.w + b.x+b.y+b.z+b.w;
    float s2 = a.x*a.x+a.y*a.y+a.z*a.z+a.w*a.w + b.x*b.x+b.y*b.y+b.z*b.z+b.w*b.w;
    #pragma unroll
    for (int o = 16; o > 0; o >>= 1) {
        s  += __shfl_xor_sync(0xffffffffu, s,  o);
        s2 += __shfl_xor_sync(0xffffffffu, s2, o);
    }
    float mu = s * (1.0f/CC);
    float rstd = rsqrtf(s2 * (1.0f/CC) - mu*mu + 1e-5f);
    float4 g0 = *reinterpret_cast<const float4*>(gam + lane*4);
    float4 g1 = *reinterpret_cast<const float4*>(gam + 128 + lane*4);
    float4 b0 = *reinterpret_cast<const float4*>(bet + lane*4);
    float4 b1 = *reinterpret_cast<const float4*>(bet + 128 + lane*4);
    __nv_bfloat162 p0 = __floats2bfloat162_rn((a.x-mu)*rstd*g0.x+b0.x, (a.y-mu)*rstd*g0.y+b0.y);
    __nv_bfloat162 p1 = __floats2bfloat162_rn((a.z-mu)*rstd*g0.z+b0.z, (a.w-mu)*rstd*g0.w+b0.w);
    __nv_bfloat162 p2 = __floats2bfloat162_rn((b.x-mu)*rstd*g1.x+b1.x, (b.y-mu)*rstd*g1.y+b1.y);
    __nv_bfloat162 p3 = __floats2bfloat162_rn((b.z-mu)*rstd*g1.z+b1.z, (b.w-mu)*rstd*g1.w+b1.w);
    uint2 u0; u0.x = *reinterpret_cast<uint32_t*>(&p0); u0.y = *reinterpret_cast<uint32_t*>(&p1);
    uint2 u1; u1.x = *reinterpret_cast<uint32_t*>(&p2); u1.y = *reinterpret_cast<uint32_t*>(&p3);
    *reinterpret_cast<uint2*>(dst + lane*4) = u0;
    *reinterpret_cast<uint2*>(dst + 128 + lane*4) = u1;
}

#define LN1_BLKS (ROWS/8)   // 12544
__global__ void __launch_bounds__(256)
preamble_kernel(const float* __restrict__ x,
                const float* __restrict__ norm1_g, const float* __restrict__ norm1_b,
                const float* __restrict__ wq, __nv_bfloat16* __restrict__ wqt,
                const float* __restrict__ wk, __nv_bfloat16* __restrict__ wkt,
                const float* __restrict__ wv, __nv_bfloat16* __restrict__ wvt,
                const float* __restrict__ wp, __nv_bfloat16* __restrict__ wpt,
                const float* __restrict__ w1, __nv_bfloat16* __restrict__ w1t,
                const float* __restrict__ w2, __nv_bfloat16* __restrict__ w2t) {
    int bid = blockIdx.x;
    if (bid < LN1_BLKS) {
        int wid = threadIdx.x >> 5, lane = threadIdx.x & 31;
        int row = bid * 8 + wid;
        int bidx = row / LL, l = row % LL;
        int h = l / WW, w = l % WW;
        int widx = (bidx*8 + h/WS)*8 + (w/WS);
        int token = (h%WS)*WS + (w%WS);
        ln_row(x + (size_t)row * CC, norm1_g, norm1_b,
               g_xw_bf + ((size_t)widx*NT + token)*CC, lane);
    } else {
        int wb = bid - LN1_BLKS;
        if      (wb < 64)  wtrans_tile(wq, wqt, 256, 256, wb);
        else if (wb < 80)  wtrans_tile(wk, wkt, 128, 128, wb - 64);
        else if (wb < 144) wtrans_tile(wv, wvt, 256, 256, wb - 80);
        else if (wb < 208) wtrans_tile(wp, wpt, 256, 256, wb - 144);
        else if (wb < 464) wtrans_tile(w1, w1t, 256, 1024, wb - 208);
        else               wtrans_tile(w2, w2t, 1024, 256, wb - 464);
    }
}

// ---------------- warp-per-row LN2 (bf16 out, linear) ----------------
__global__ void __launch_bounds__(256)
ln2_warp_kernel(const float* __restrict__ x,
                const float* __restrict__ gam, const float* __restrict__ bet) {
    int wid = threadIdx.x >> 5, lane = threadIdx.x & 31;
    int row = blockIdx.x * 8 + wid;
    ln_row(x + (size_t)row * CC, gam, bet, g_xn2_bf + (size_t)row * CC, lane);
}

// ---------------- warp-per-(window,head) top-k + gathers (bf16 q) ----------------
#define TKQT  (NT*33)
#define TKREG (TKQT + 49 + 28 + 2)
#define TOPK_SMEM (8*TKREG*4)

__global__ void __launch_bounds__(256)
topk_warp_kernel(const float* __restrict__ wch, const float* __restrict__ bch) {
    extern __shared__ float tsm[];
    int wid = threadIdx.x >> 5, lane = threadIdx.x & 31;
    float* qt  = tsm + wid * TKREG;
    float* tm  = qt + TKQT;
    int*   sidx = (int*)(tm + 49);
    int bn = blockIdx.x * 8 + wid;
    int widx = bn >> 3, nh = bn & 7;

    const __nv_bfloat16* base = g_q_bf + (size_t)widx*NT*CC + nh*HD + lane;
    float cs = 0.0f, cm = -1e30f;
    #pragma unroll
    for (int t = 0; t < NT; t++) {
        float v = __bfloat162float(base[(size_t)t*CC]);
        qt[t*33 + lane] = v;
        cs += v; cm = fmaxf(cm, v);
    }
    float cmean = cs * (1.0f/NT);
    __syncwarp();

    for (int t = lane; t < NT; t += 32) {
        float s = 0.0f;
        #pragma unroll
        for (int hd = 0; hd < HD; hd++) s += qt[t*33 + hd];
        tm[t] = s * (1.0f/HD);
    }
    __syncwarp();

    float sc = bch[lane];
    #pragma unroll
    for (int i = 0; i < HD; i++) {
        float cmi = __shfl_sync(0xffffffffu, cmean, i);
        float cxi = __shfl_sync(0xffffffffu, cm, i);
        sc += cmi * wch[i*HD + lane] + cxi * wch[(HD+i)*HD + lane];
    }
    sc = gelu_exact(sc);

    int cnt = 0;
    #pragma unroll
    for (int j = 0; j < HD; j++) {
        float sj = __shfl_sync(0xffffffffu, sc, j);
        cnt += (sj > sc) || (sj == sc && j < lane);
    }
    int cflag = cnt < KCH;
    unsigned cmask = __ballot_sync(0xffffffffu, cflag);
    int cpos = __popc(cmask & ((1u << lane) - 1u));

    float t0v = tm[lane];
    float t1v = (lane + 32 < NT) ? tm[lane + 32] : -1e30f;
    int scnt0 = 0, scnt1 = 0;
    #pragma unroll
    for (int j = 0; j < NT; j++) {
        float tj = tm[j];
        scnt0 += (tj > t0v) || (tj == t0v && j < lane);
        scnt1 += (tj > t1v) || (tj == t1v && j < lane + 32);
    }
    int sflag0 = scnt0 < KSPT;
    int sflag1 = (lane + 32 < NT) && (scnt1 < KSPT);
    unsigned m0 = __ballot_sync(0xffffffffu, sflag0);
    unsigned m1 = __ballot_sync(0xffffffffu, sflag1);
    if (sflag0) sidx[__popc(m0 & ((1u << lane) - 1u))] = lane;
    if (sflag1) sidx[__popc(m0) + __popc(m1 & ((1u << lane) - 1u))] = lane + 32;
    __syncwarp();

    if (cflag) {
        __nv_bfloat16* dst = g_qcha1_bf + (size_t)widx*NT*(CC/2) + nh*KCH + cpos;
        #pragma unroll
        for (int t = 0; t < NT; t++)
            dst[(size_t)t*(CC/2)] = __float2bfloat16(qt[t*33 + lane]);
    }
    {
        __nv_bfloat16* dst = g_vbuf_bf + (size_t)widx*KSPT*CC + nh*HD + lane;
        #pragma unroll
        for (int s = 0; s < KSPT; s++) {
            int t = sidx[s];
            dst[(size_t)s*CC] = __float2bfloat16(qt[t*33 + lane]);
        }
    }
    if (lane < KSPT) g_sidx[bn*KSPT + lane] = sidx[lane];
}

// ---------------- warp-per-(window,head) attention ----------------
__global__ void __launch_bounds__(256)
attn_warp_kernel(const float* __restrict__ rpb) {
    __shared__ float khs[8][NT*KCH];
    int wid = threadIdx.x >> 5, lane = threadIdx.x & 31;
    int bn = blockIdx.x * 8 + wid;
    int widx = bn >> 3, nh = bn & 7;
    float* kh = khs[wid];

    for (int t = lane; t < NT; t += 32) {
        const __nv_bfloat16* src = g_k_bf + ((size_t)widx*NT + t)*(CC/2) + nh*KCH;
        uint4 a = *reinterpret_cast<const uint4*>(src);
        uint4 b = *reinterpret_cast<const uint4*>(src + 8);
        const __nv_bfloat16* pa = reinterpret_cast<const __nv_bfloat16*>(&a);
        const __nv_bfloat16* pb = reinterpret_cast<const __nv_bfloat16*>(&b);
        #pragma unroll
        for (int j = 0; j < 8; j++) kh[t*KCH + j]     = __bfloat162float(pa[j]);
        #pragma unroll
        for (int j = 0; j < 8; j++) kh[t*KCH + 8 + j] = __bfloat162float(pb[j]);
    }

    float vreg[KSPT];
    #pragma unroll
    for (int s = 0; s < KSPT; s++)
        vreg[s] = __bfloat162float(g_vproj_bf[((size_t)widx*KSPT + s)*CC + nh*HD + lane]);

    float qa[KCH];
    int r2 = 0, c2 = 0;
    if (lane < KSPT) {
        int t2 = g_sidx[bn*KSPT + lane];
        r2 = t2 / WS; c2 = t2 % WS;
        const __nv_bfloat16* src = g_qcha1_bf + ((size_t)widx*NT + t2)*(CC/2) + nh*KCH;
        uint4 a = *reinterpret_cast<const uint4*>(src);
        uint4 b = *reinterpret_cast<const uint4*>(src + 8);
        const __nv_bfloat16* pa = reinterpret_cast<const __nv_bfloat16*>(&a);
        const __nv_bfloat16* pb = reinterpret_cast<const __nv_bfloat16*>(&b);
        #pragma unroll
        for (int j = 0; j < 8; j++) qa[j]     = __bfloat162float(pa[j]) * SCALE_F;
        #pragma unroll
        for (int j = 0; j < 8; j++) qa[8 + j] = __bfloat162float(pb[j]) * SCALE_F;
    } else {
        #pragma unroll
        for (int j = 0; j < KCH; j++) qa[j] = 0.0f;
    }
    __syncwarp();

    __nv_bfloat16* obase = g_obuf_bf + (size_t)widx*NT*CC + nh*HD + lane;
    const float inv_kspt = 1.0f / KSPT;
    for (int t = 0; t < NT; t++) {
        float sum = 0.0f;
        #pragma unroll
        for (int j = 0; j < KCH; j++) sum += kh[t*KCH + j] * qa[j];
        int rt = t / WS, ct = t % WS;
        int rel = (rt - r2 + WS - 1) * (2*WS - 1) + (ct - c2 + WS - 1);
        float at = sum + rpb[rel*NH + nh];
        if (lane >= KSPT) at = -1e30f;
        float m = at;
        #pragma unroll
        for (int o = 16; o > 0; o >>= 1) m = fmaxf(m, __shfl_xor_sync(0xffffffffu, m, o));
        float araw = (lane < KSPT) ? at : 0.0f;
        #pragma unroll
        for (int o = 16; o > 0; o >>= 1) araw += __shfl_xor_sync(0xffffffffu, araw, o);
        float gate = 1.0f / (1.0f + expf(-araw * inv_kspt));
        float e = expf(at - m);
        float es = e;
        #pragma unroll
        for (int o = 16; o > 0; o >>= 1) es += __shfl_xor_sync(0xffffffffu, es, o);
        float p = e * (gate / es);
        float acc = 0.0f;
        #pragma unroll
        for (int s = 0; s < KSPT; s++)
            acc += __shfl_sync(0xffffffffu, p, s) * vreg[s];
        obase[(size_t)t*CC] = __float2bfloat16(acc);
    }
}

// ---------------- launch ----------------
extern "C" void kernel_launch(void* const* d_in, const int* in_sizes, int n_in,
                              void* d_out, int out_size) {
    const float* x       = (const float*)d_in[0];
    const float* norm1_g = (const float*)d_in[1];
    const float* norm1_b = (const float*)d_in[2];
    const float* wq      = (const float*)d_in[3];
    const float* bq      = (const float*)d_in[4];
    const float* wk      = (const float*)d_in[5];
    const float* bk      = (const float*)d_in[6];
    const float* wv      = (const float*)d_in[7];
    const float* bv      = (const float*)d_in[8];
    const float* wproj   = (const float*)d_in[9];
    const float* bproj   = (const float*)d_in[10];
    const float* wch     = (const float*)d_in[11];
    const float* bch     = (const float*)d_in[12];
    const float* rpb     = (const float*)d_in[13];
    const float* norm2_g = (const float*)d_in[14];
    const float* norm2_b = (const float*)d_in[15];
    const float* w1      = (const float*)d_in[16];
    const float* b1      = (const float*)d_in[17];
    const float* w2      = (const float*)d_in[18];
    const float* b2      = (const float*)d_in[19];
    float* out = (float*)d_out;

    __nv_bfloat16 *p_xw_bf, *p_q_bf, *p_qcha1_bf, *p_k_bf, *p_vbuf_bf, *p_vproj_bf, *p_obuf_bf, *p_xn2_bf, *p_h_bf;
    __nv_bfloat16 *p_wq_t, *p_wk_t, *p_wv_t, *p_wproj_t, *p_w1_t, *p_w2_t;
    cudaGetSymbolAddress((void**)&p_xw_bf, g_xw_bf);
    cudaGetSymbolAddress((void**)&p_q_bf, g_q_bf);
    cudaGetSymbolAddress((void**)&p_qcha1_bf, g_qcha1_bf);
    cudaGetSymbolAddress((void**)&p_k_bf, g_k_bf);
    cudaGetSymbolAddress((void**)&p_vbuf_bf, g_vbuf_bf);
    cudaGetSymbolAddress((void**)&p_vproj_bf, g_vproj_bf);
    cudaGetSymbolAddress((void**)&p_obuf_bf, g_obuf_bf);
    cudaGetSymbolAddress((void**)&p_xn2_bf, g_xn2_bf);
    cudaGetSymbolAddress((void**)&p_h_bf, g_h_bf);
    cudaGetSymbolAddress((void**)&p_wq_t, g_wq_t);
    cudaGetSymbolAddress((void**)&p_wk_t, g_wk_t);
    cudaGetSymbolAddress((void**)&p_wv_t, g_wv_t);
    cudaGetSymbolAddress((void**)&p_wproj_t, g_wproj_t);
    cudaGetSymbolAddress((void**)&p_w1_t, g_w1_t);
    cudaGetSymbolAddress((void**)&p_w2_t, g_w2_t);

    cudaFuncSetAttribute(gemm_bf16_kernel<0,1,0,0>, cudaFuncAttributeMaxDynamicSharedMemorySize, GEMM_SMEM);
    cudaFuncSetAttribute(gemm_bf16_kernel<0,0,1,0>, cudaFuncAttributeMaxDynamicSharedMemorySize, GEMM_SMEM);
    cudaFuncSetAttribute(gemm_bf16_kernel<0,1,0,1>, cudaFuncAttributeMaxDynamicSharedMemorySize, GEMM_SMEM);
    cudaFuncSetAttribute(gemm_bf16_kernel<1,0,1,0>, cudaFuncAttributeMaxDynamicSharedMemorySize, GEMM_SMEM);
    cudaFuncSetAttribute(kv_gemm_kernel, cudaFuncAttributeMaxDynamicSharedMemorySize, GEMM_SMEM);
    cudaFuncSetAttribute(topk_warp_kernel, cudaFuncAttributeMaxDynamicSharedMemorySize, TOPK_SMEM);

    // 1) merged preamble: LN1+window partition (warp per row) + all weight transposes
    preamble_kernel<<<LN1_BLKS + 720, 256>>>(x, norm1_g, norm1_b,
                                             wq, p_wq_t, wk, p_wk_t, wv, p_wv_t,
                                             wproj, p_wproj_t, w1, p_w1_t, w2, p_w2_t);
    // 2) q = xw @ wq + bq -> g_q_bf (bf16)
    gemm_bf16_kernel<0,0,1,0><<<dim3(CC/128, ROWS/128), 256, GEMM_SMEM>>>(
        p_xw_bf, p_wq_t, bq, nullptr, nullptr, p_q_bf, ROWS, CC, CC);
    // 3) top-k + gathers (warp per unit)
    topk_warp_kernel<<<BN/8, 256, TOPK_SMEM>>>(wch, bch);
    // 4+5) merged k-GEMM + v-GEMM (wave merging)
    kv_gemm_kernel<<<KV_TOTAL, 256, GEMM_SMEM>>>(
        p_qcha1_bf, p_wk_t, bk, p_vbuf_bf, p_wv_t, bv, p_k_bf, p_vproj_bf);
    // 6) attention (warp per unit) -> g_obuf_bf
    attn_warp_kernel<<<BN/8, 256>>>(rpb);
    // 7) proj + window reverse + residual -> d_out (fused)
    gemm_bf16_kernel<0,1,0,1><<<dim3(CC/128, ROWS/128), 256, GEMM_SMEM>>>(
        p_obuf_bf, p_wproj_t, bproj, x, out, nullptr, ROWS, CC, CC);
    // 8) LN2(d_out) -> g_xn2_bf (warp per row)
    ln2_warp_kernel<<<ROWS/8, 256>>>(out, norm2_g, norm2_b);
    // 9) h = gelu(xn2 @ w1 + b1) -> g_h_bf (bf16 only)
    gemm_bf16_kernel<1,0,1,0><<<dim3(MLPH/128, ROWS/128), 256, GEMM_SMEM>>>(
        p_xn2_bf, p_w1_t, b1, nullptr, nullptr, p_h_bf, ROWS, CC, MLPH);
    // 10) out = out + h @ w2 + b2
    gemm_bf16_kernel<0,1,0,0><<<dim3(CC/128, ROWS/128), 256, GEMM_SMEM>>>(
        p_h_bf, p_w2_t, b2, out, out, nullptr, ROWS, MLPH, CC);
}